// round 7
// baseline (speedup 1.0000x reference)
#include <cuda_runtime.h>
#include <cstdint>

#define NNODES 100000
#define FDIM   128
#define NTILES ((NNODES + 127) / 128)

// ---- device-global scratch (allocations forbidden) ----
__device__ float g_LfP[(size_t)NNODES * FDIM];   // Lf + feat   (GEMM A, k 0..127)
__device__ float g_P  [(size_t)NNODES * FDIM];   // Lf * feat   (spmm2 input)
__device__ float g_Li [(size_t)NNODES * FDIM];   // A @ P       (GEMM A, k 128..255)
__device__ int   g_rowcnt[NNODES];
__device__ int   g_rowptr[NNODES + 1];
__device__ int   g_rowcur[NNODES];
__device__ int2  g_csr[1600000 + 1024];          // (col, float_bits(val)) packed

#define SCAN_B 1024
#define SCAN_G ((NNODES + SCAN_B - 1) / SCAN_B)  // 98
__device__ int g_bsum[SCAN_G];

// ---------------------------------------------------------------------------
// CSR build: zero counts -> histogram -> 3-stage scan -> scatter
// ---------------------------------------------------------------------------
__global__ void zero_counts_kernel() {
    int i = blockIdx.x * blockDim.x + threadIdx.x;
    if (i < NNODES) g_rowcnt[i] = 0;
}

__global__ void hist_kernel(const int* __restrict__ erow, int nnz) {
    int i = (blockIdx.x * blockDim.x + threadIdx.x) * 4;
    if (i + 3 < nnz) {
        int4 r = *reinterpret_cast<const int4*>(erow + i);
        atomicAdd(&g_rowcnt[r.x], 1);
        atomicAdd(&g_rowcnt[r.y], 1);
        atomicAdd(&g_rowcnt[r.z], 1);
        atomicAdd(&g_rowcnt[r.w], 1);
    } else {
        for (int j = i; j < nnz; j++) atomicAdd(&g_rowcnt[erow[j]], 1);
    }
}

__global__ __launch_bounds__(SCAN_B)
void scan_partial_kernel() {
    __shared__ int s[SCAN_B];
    int tid = threadIdx.x;
    int i = blockIdx.x * SCAN_B + tid;
    s[tid] = (i < NNODES) ? g_rowcnt[i] : 0;
    __syncthreads();
    for (int off = SCAN_B >> 1; off > 0; off >>= 1) {
        if (tid < off) s[tid] += s[tid + off];
        __syncthreads();
    }
    if (tid == 0) g_bsum[blockIdx.x] = s[0];
}

__global__ __launch_bounds__(128, 1)
void scan_bsum_kernel() {
    __shared__ int s[128];
    int tid = threadIdx.x;
    int v = (tid < SCAN_G) ? g_bsum[tid] : 0;
    s[tid] = v;
    __syncthreads();
    for (int off = 1; off < 128; off <<= 1) {
        int t = (tid >= off) ? s[tid - off] : 0;
        __syncthreads();
        s[tid] += t;
        __syncthreads();
    }
    if (tid < SCAN_G) g_bsum[tid] = s[tid] - v;   // exclusive
}

__global__ __launch_bounds__(SCAN_B)
void scan_final_kernel() {
    __shared__ int s[SCAN_B];
    int tid = threadIdx.x;
    int i = blockIdx.x * SCAN_B + tid;
    int v = (i < NNODES) ? g_rowcnt[i] : 0;
    s[tid] = v;
    __syncthreads();
    for (int off = 1; off < SCAN_B; off <<= 1) {
        int t = (tid >= off) ? s[tid - off] : 0;
        __syncthreads();
        s[tid] += t;
        __syncthreads();
    }
    int excl = s[tid] - v + g_bsum[blockIdx.x];
    if (i < NNODES) {
        g_rowptr[i] = excl;
        g_rowcur[i] = excl;
        if (i == NNODES - 1) g_rowptr[NNODES] = excl + v;
    }
}

__global__ void scatter_kernel(const float* __restrict__ eval,
                               const int*   __restrict__ erow,
                               const int*   __restrict__ ecol,
                               int nnz) {
    int i = (blockIdx.x * blockDim.x + threadIdx.x) * 4;
    if (i + 3 < nnz) {
        int4   r = *reinterpret_cast<const int4*>(erow + i);
        int4   c = *reinterpret_cast<const int4*>(ecol + i);
        float4 v = *reinterpret_cast<const float4*>(eval + i);
        int p0 = atomicAdd(&g_rowcur[r.x], 1);
        int p1 = atomicAdd(&g_rowcur[r.y], 1);
        int p2 = atomicAdd(&g_rowcur[r.z], 1);
        int p3 = atomicAdd(&g_rowcur[r.w], 1);
        g_csr[p0] = make_int2(c.x, __float_as_int(v.x));
        g_csr[p1] = make_int2(c.y, __float_as_int(v.y));
        g_csr[p2] = make_int2(c.z, __float_as_int(v.z));
        g_csr[p3] = make_int2(c.w, __float_as_int(v.w));
    } else {
        for (int j = i; j < nnz; j++) {
            int pos = atomicAdd(&g_rowcur[erow[j]], 1);
            g_csr[pos] = make_int2(ecol[j], __float_as_int(eval[j]));
        }
    }
}

// ---------------------------------------------------------------------------
// SpMM-CSR, warp per row. Register accumulate, plain stores.
// ---------------------------------------------------------------------------
__global__ __launch_bounds__(256)
void spmm1_csr_kernel(const float* __restrict__ feat) {
    int row = blockIdx.x * (blockDim.x >> 5) + (threadIdx.x >> 5);
    if (row >= NNODES) return;
    int lane = threadIdx.x & 31;
    int beg = g_rowptr[row];
    int end = g_rowptr[row + 1];

    float4 acc = make_float4(0.f, 0.f, 0.f, 0.f);
    for (int base = beg; base < end; base += 32) {
        int cnt = min(32, end - base);
        int   mycol = 0;
        float myval = 0.f;
        if (lane < cnt) {
            int2 e = g_csr[base + lane];
            mycol = e.x;
            myval = __int_as_float(e.y);
        }
        #pragma unroll 8
        for (int j = 0; j < cnt; j++) {
            int   c = __shfl_sync(0xffffffffu, mycol, j);
            float v = __shfl_sync(0xffffffffu, myval, j);
            float4 x = reinterpret_cast<const float4*>(feat + (size_t)c * FDIM)[lane];
            acc.x = fmaf(v, x.x, acc.x);
            acc.y = fmaf(v, x.y, acc.y);
            acc.z = fmaf(v, x.z, acc.z);
            acc.w = fmaf(v, x.w, acc.w);
        }
    }
    float4 ft = reinterpret_cast<const float4*>(feat + (size_t)row * FDIM)[lane];
    float4 lp = make_float4(acc.x + ft.x, acc.y + ft.y, acc.z + ft.z, acc.w + ft.w);
    float4 pp = make_float4(acc.x * ft.x, acc.y * ft.y, acc.z * ft.z, acc.w * ft.w);
    reinterpret_cast<float4*>(g_LfP + (size_t)row * FDIM)[lane] = lp;
    reinterpret_cast<float4*>(g_P   + (size_t)row * FDIM)[lane] = pp;
}

__global__ __launch_bounds__(256)
void spmm2_csr_kernel() {
    int row = blockIdx.x * (blockDim.x >> 5) + (threadIdx.x >> 5);
    if (row >= NNODES) return;
    int lane = threadIdx.x & 31;
    int beg = g_rowptr[row];
    int end = g_rowptr[row + 1];

    float4 acc = make_float4(0.f, 0.f, 0.f, 0.f);
    for (int base = beg; base < end; base += 32) {
        int cnt = min(32, end - base);
        int   mycol = 0;
        float myval = 0.f;
        if (lane < cnt) {
            int2 e = g_csr[base + lane];
            mycol = e.x;
            myval = __int_as_float(e.y);
        }
        #pragma unroll 8
        for (int j = 0; j < cnt; j++) {
            int   c = __shfl_sync(0xffffffffu, mycol, j);
            float v = __shfl_sync(0xffffffffu, myval, j);
            float4 x = reinterpret_cast<const float4*>(g_P + (size_t)c * FDIM)[lane];
            acc.x = fmaf(v, x.x, acc.x);
            acc.y = fmaf(v, x.y, acc.y);
            acc.z = fmaf(v, x.z, acc.z);
            acc.w = fmaf(v, x.w, acc.w);
        }
    }
    reinterpret_cast<float4*>(g_Li + (size_t)row * FDIM)[lane] = acc;
}

// ---------------------------------------------------------------------------
// Persistent tensor-core GEMM (mma.sync m16n8k8 tf32), k-interleaved smem:
//   element (n|r, k) stored at column kI = (k&~7) + (k&3)*2 + ((k>>2)&1)
//   -> fragment pairs (k, k+4) are adjacent -> all frag loads are LDS.64.
// Strides 136/264 floats: 8B-bank index = 4*gid + tg -> conflict-free.
// ---------------------------------------------------------------------------
#define WT_STRIDE 264
#define AS_STRIDE 136
#define OFF_WT 0
#define OFF_AS (128 * WT_STRIDE * 4)                  // 135168
#define OFF_BI (OFF_AS + 128 * AS_STRIDE * 4)         // 204800
#define SMEM_GEMM (OFF_BI + 512)                      // 205312

static __device__ __forceinline__ uint32_t f2tf32(float f) {
    uint32_t u;
    asm("cvt.rna.tf32.f32 %0, %1;" : "=r"(u) : "f"(f));
    return u;
}

static __device__ __forceinline__ void mma8(float* d, uint32_t a0, uint32_t a1,
                                            uint32_t a2, uint32_t a3,
                                            uint32_t b0, uint32_t b1) {
    asm volatile(
        "mma.sync.aligned.m16n8k8.row.col.f32.tf32.tf32.f32 "
        "{%0,%1,%2,%3}, {%4,%5,%6,%7}, {%8,%9}, {%0,%1,%2,%3};"
        : "+f"(d[0]), "+f"(d[1]), "+f"(d[2]), "+f"(d[3])
        : "r"(a0), "r"(a1), "r"(a2), "r"(a3), "r"(b0), "r"(b1));
}

__global__ __launch_bounds__(256, 1)
void gemm_mma_kernel(const float* __restrict__ W1,
                     const float* __restrict__ b1,
                     const float* __restrict__ W2,
                     const float* __restrict__ b2,
                     float* __restrict__ out) {
    extern __shared__ char smem[];
    uint32_t* Wt   = reinterpret_cast<uint32_t*>(smem + OFF_WT);  // [128][264]
    uint32_t* As   = reinterpret_cast<uint32_t*>(smem + OFF_AS);  // [128][136]
    float*    bias = reinterpret_cast<float*>(smem + OFF_BI);

    const int tid  = threadIdx.x;
    const int w    = tid >> 5;
    const int lane = tid & 31;
    const int tg   = lane & 3;    // k within frag
    const int gid  = lane >> 2;   // row/col within frag
    const int wm   = w & 3;       // row-group
    const int colg = w >> 2;      // col-group

    // ---- stage Wt[n][kI] = tf32(W[k][n]) ONCE (k-interleaved) ----
    #pragma unroll
    for (int it = 0; it < 32; it++) {
        int wt = it * 8 + w;                 // 0..255 warp-tasks
        int k0 = (wt >> 2) * 4;              // 0..252 step 4
        int n  = (wt & 3) * 32 + lane;       // 0..127
        const float* Wsrc = (k0 < 128) ? (W1 + (size_t)k0 * 128)
                                       : (W2 + (size_t)(k0 - 128) * 128);
        // kI for k0..k0+3: (k0&~7) + d*2 + ((k0>>2)&1)
        int kb  = (k0 & ~7) + ((k0 >> 2) & 1);
        uint32_t* dst = Wt + n * WT_STRIDE + kb;
        dst[0] = f2tf32(Wsrc[0 * 128 + n]);
        dst[2] = f2tf32(Wsrc[1 * 128 + n]);
        dst[4] = f2tf32(Wsrc[2 * 128 + n]);
        dst[6] = f2tf32(Wsrc[3 * 128 + n]);
    }
    if (tid < 128) bias[tid] = b1[tid] + b2[tid];

    for (int tile = blockIdx.x; tile < NTILES; tile += gridDim.x) {
        const int row0 = tile * 128;

        float acc[2][8][4];
        #pragma unroll
        for (int s = 0; s < 2; s++)
            #pragma unroll
            for (int nt = 0; nt < 8; nt++)
                #pragma unroll
                for (int q = 0; q < 4; q++) acc[s][nt][q] = 0.f;

        #pragma unroll
        for (int phase = 0; phase < 2; phase++) {
            const float* src = phase ? g_Li : g_LfP;
            __syncthreads();   // Wt ready / As free

            // ---- stage As[r][kI] = tf32(src row), 8 floats per thread-task ----
            #pragma unroll
            for (int it = 0; it < 8; it++) {
                int idx = it * 256 + tid;    // 0..2047
                int r  = idx >> 4;           // 0..127
                int j8 = (idx & 15) * 8;     // 0..120 step 8
                int row = row0 + r;
                if (row >= NNODES) row = NNODES - 1;
                const float4* sp = reinterpret_cast<const float4*>(
                                       src + (size_t)row * FDIM + j8);
                float4 v0 = sp[0];           // k = j8..j8+3
                float4 v1 = sp[1];           // k = j8+4..j8+7
                uint32_t* dst = As + r * AS_STRIDE + j8;
                // interleave: [k, k+4] adjacent
                *reinterpret_cast<uint2*>(dst + 0) =
                    make_uint2(f2tf32(v0.x), f2tf32(v1.x));
                *reinterpret_cast<uint2*>(dst + 2) =
                    make_uint2(f2tf32(v0.y), f2tf32(v1.y));
                *reinterpret_cast<uint2*>(dst + 4) =
                    make_uint2(f2tf32(v0.z), f2tf32(v1.z));
                *reinterpret_cast<uint2*>(dst + 6) =
                    make_uint2(f2tf32(v0.w), f2tf32(v1.w));
            }
            __syncthreads();

            const int kg0 = phase * 128;
            #pragma unroll 2
            for (int kb = 0; kb < 128; kb += 8) {
                // A fragments: LDS.64 pairs (a0,a2) and (a1,a3)
                uint2 aA[2], aB[2];
                #pragma unroll
                for (int sub = 0; sub < 2; sub++) {
                    int rb = wm * 32 + sub * 16 + gid;
                    aA[sub] = *reinterpret_cast<const uint2*>(
                        As + rb * AS_STRIDE + kb + tg * 2);
                    aB[sub] = *reinterpret_cast<const uint2*>(
                        As + (rb + 8) * AS_STRIDE + kb + tg * 2);
                }
                #pragma unroll
                for (int nt = 0; nt < 8; nt++) {
                    int n = colg * 64 + nt * 8 + gid;
                    uint2 b01 = *reinterpret_cast<const uint2*>(
                        Wt + n * WT_STRIDE + kg0 + kb + tg * 2);
                    mma8(acc[0][nt], aA[0].x, aB[0].x, aA[0].y, aB[0].y,
                         b01.x, b01.y);
                    mma8(acc[1][nt], aA[1].x, aB[1].x, aA[1].y, aB[1].y,
                         b01.x, b01.y);
                }
            }
        }

        // ---- epilogue: add bias, float2 stores ----
        #pragma unroll
        for (int sub = 0; sub < 2; sub++) {
            int r0 = row0 + wm * 32 + sub * 16 + gid;
            #pragma unroll
            for (int nt = 0; nt < 8; nt++) {
                int c = colg * 64 + nt * 8 + tg * 2;
                float bx = bias[c], by = bias[c + 1];
                if (r0 < NNODES) {
                    float2 o = make_float2(acc[sub][nt][0] + bx, acc[sub][nt][1] + by);
                    *reinterpret_cast<float2*>(out + (size_t)r0 * FDIM + c) = o;
                }
                if (r0 + 8 < NNODES) {
                    float2 o = make_float2(acc[sub][nt][2] + bx, acc[sub][nt][3] + by);
                    *reinterpret_cast<float2*>(out + (size_t)(r0 + 8) * FDIM + c) = o;
                }
            }
        }
    }
}

// ---------------------------------------------------------------------------
extern "C" void kernel_launch(void* const* d_in, const int* in_sizes, int n_in,
                              void* d_out, int out_size) {
    const float* feat = (const float*)d_in[0];
    const float* eval = (const float*)d_in[1];
    const float* W1   = (const float*)d_in[2];
    const float* b1   = (const float*)d_in[3];
    const float* W2   = (const float*)d_in[4];
    const float* b2   = (const float*)d_in[5];
    const int*   erow = (const int*)d_in[6];
    const int*   ecol = (const int*)d_in[7];
    float*       out  = (float*)d_out;

    const int nnz = in_sizes[1];

    // CSR build
    zero_counts_kernel<<<(NNODES + 255) / 256, 256>>>();
    hist_kernel<<<(nnz / 4 + 255) / 256, 256>>>(erow, nnz);
    scan_partial_kernel<<<SCAN_G, SCAN_B>>>();
    scan_bsum_kernel<<<1, 128>>>();
    scan_final_kernel<<<SCAN_G, SCAN_B>>>();
    scatter_kernel<<<(nnz / 4 + 255) / 256, 256>>>(eval, erow, ecol, nnz);

    // SpMM passes (warp per row)
    {
        int blocks = (NNODES + 7) / 8;
        spmm1_csr_kernel<<<blocks, 256>>>(feat);
        spmm2_csr_kernel<<<blocks, 256>>>();
    }

    // GEMM (persistent, mma.sync tf32, LDS.64 fragments)
    {
        cudaFuncSetAttribute(gemm_mma_kernel,
                             cudaFuncAttributeMaxDynamicSharedMemorySize,
                             SMEM_GEMM);
        gemm_mma_kernel<<<148, 256, SMEM_GEMM>>>(W1, b1, W2, b2, out);
    }
}

// round 8
// speedup vs baseline: 1.1889x; 1.1889x over previous
#include <cuda_runtime.h>
#include <cuda_fp16.h>
#include <cstdint>

#define NNODES 100000
#define FDIM   128
#define NTILES ((NNODES + 127) / 128)

// ---- device-global scratch (allocations forbidden) ----
__device__ float  g_LfP[(size_t)NNODES * FDIM];  // Lf + feat   (GEMM A, k 0..127)
__device__ float  g_Li [(size_t)NNODES * FDIM];  // A @ P       (GEMM A, k 128..255)
__device__ __half g_featH[(size_t)NNODES * FDIM];// fp16 copy of features
__device__ __half g_PH  [(size_t)NNODES * FDIM]; // Lf * feat in fp16 (spmm2 input)
__device__ int    g_rowcnt[NNODES];
__device__ int    g_rowptr[NNODES + 1];
__device__ int    g_rowcur[NNODES];
__device__ int2   g_csr[1600000 + 1024];         // (col, float_bits(val)) packed

#define SCAN_B 1024
#define SCAN_G ((NNODES + SCAN_B - 1) / SCAN_B)  // 98
__device__ int g_bsum[SCAN_G];

// ---------------------------------------------------------------------------
// feat -> fp16 copy (streaming)
// ---------------------------------------------------------------------------
__global__ void cvt_feat_kernel(const float* __restrict__ feat) {
    size_t i = (size_t)blockIdx.x * blockDim.x + threadIdx.x;   // per 8 floats
    const size_t total = (size_t)NNODES * FDIM / 8;
    if (i < total) {
        const float4* s = reinterpret_cast<const float4*>(feat) + i * 2;
        float4 a = s[0], b = s[1];
        __half2 h0 = __floats2half2_rn(a.x, a.y);
        __half2 h1 = __floats2half2_rn(a.z, a.w);
        __half2 h2 = __floats2half2_rn(b.x, b.y);
        __half2 h3 = __floats2half2_rn(b.z, b.w);
        uint4 st = make_uint4(*reinterpret_cast<uint32_t*>(&h0),
                              *reinterpret_cast<uint32_t*>(&h1),
                              *reinterpret_cast<uint32_t*>(&h2),
                              *reinterpret_cast<uint32_t*>(&h3));
        reinterpret_cast<uint4*>(g_featH)[i] = st;
    }
}

// ---------------------------------------------------------------------------
// CSR build: zero counts -> histogram -> 3-stage scan -> scatter
// ---------------------------------------------------------------------------
__global__ void zero_counts_kernel() {
    int i = blockIdx.x * blockDim.x + threadIdx.x;
    if (i < NNODES) g_rowcnt[i] = 0;
}

__global__ void hist_kernel(const int* __restrict__ erow, int nnz) {
    int i = (blockIdx.x * blockDim.x + threadIdx.x) * 4;
    if (i + 3 < nnz) {
        int4 r = *reinterpret_cast<const int4*>(erow + i);
        atomicAdd(&g_rowcnt[r.x], 1);
        atomicAdd(&g_rowcnt[r.y], 1);
        atomicAdd(&g_rowcnt[r.z], 1);
        atomicAdd(&g_rowcnt[r.w], 1);
    } else {
        for (int j = i; j < nnz; j++) atomicAdd(&g_rowcnt[erow[j]], 1);
    }
}

__global__ __launch_bounds__(SCAN_B)
void scan_partial_kernel() {
    __shared__ int s[SCAN_B];
    int tid = threadIdx.x;
    int i = blockIdx.x * SCAN_B + tid;
    s[tid] = (i < NNODES) ? g_rowcnt[i] : 0;
    __syncthreads();
    for (int off = SCAN_B >> 1; off > 0; off >>= 1) {
        if (tid < off) s[tid] += s[tid + off];
        __syncthreads();
    }
    if (tid == 0) g_bsum[blockIdx.x] = s[0];
}

__global__ __launch_bounds__(128, 1)
void scan_bsum_kernel() {
    __shared__ int s[128];
    int tid = threadIdx.x;
    int v = (tid < SCAN_G) ? g_bsum[tid] : 0;
    s[tid] = v;
    __syncthreads();
    for (int off = 1; off < 128; off <<= 1) {
        int t = (tid >= off) ? s[tid - off] : 0;
        __syncthreads();
        s[tid] += t;
        __syncthreads();
    }
    if (tid < SCAN_G) g_bsum[tid] = s[tid] - v;   // exclusive
}

__global__ __launch_bounds__(SCAN_B)
void scan_final_kernel() {
    __shared__ int s[SCAN_B];
    int tid = threadIdx.x;
    int i = blockIdx.x * SCAN_B + tid;
    int v = (i < NNODES) ? g_rowcnt[i] : 0;
    s[tid] = v;
    __syncthreads();
    for (int off = 1; off < SCAN_B; off <<= 1) {
        int t = (tid >= off) ? s[tid - off] : 0;
        __syncthreads();
        s[tid] += t;
        __syncthreads();
    }
    int excl = s[tid] - v + g_bsum[blockIdx.x];
    if (i < NNODES) {
        g_rowptr[i] = excl;
        g_rowcur[i] = excl;
        if (i == NNODES - 1) g_rowptr[NNODES] = excl + v;
    }
}

__global__ void scatter_kernel(const float* __restrict__ eval,
                               const int*   __restrict__ erow,
                               const int*   __restrict__ ecol,
                               int nnz) {
    int i = (blockIdx.x * blockDim.x + threadIdx.x) * 4;
    if (i + 3 < nnz) {
        int4   r = *reinterpret_cast<const int4*>(erow + i);
        int4   c = *reinterpret_cast<const int4*>(ecol + i);
        float4 v = *reinterpret_cast<const float4*>(eval + i);
        int p0 = atomicAdd(&g_rowcur[r.x], 1);
        int p1 = atomicAdd(&g_rowcur[r.y], 1);
        int p2 = atomicAdd(&g_rowcur[r.z], 1);
        int p3 = atomicAdd(&g_rowcur[r.w], 1);
        g_csr[p0] = make_int2(c.x, __float_as_int(v.x));
        g_csr[p1] = make_int2(c.y, __float_as_int(v.y));
        g_csr[p2] = make_int2(c.z, __float_as_int(v.z));
        g_csr[p3] = make_int2(c.w, __float_as_int(v.w));
    } else {
        for (int j = i; j < nnz; j++) {
            int pos = atomicAdd(&g_rowcur[erow[j]], 1);
            g_csr[pos] = make_int2(ecol[j], __float_as_int(eval[j]));
        }
    }
}

// ---------------------------------------------------------------------------
// SpMM-CSR, warp per row, fp16 gathers, fp32 accumulate.
// Lane owns cols lane*4..lane*4+3 (8 bytes fp16 per gather row).
// ---------------------------------------------------------------------------
__global__ __launch_bounds__(256)
void spmm1_csr_kernel(const float* __restrict__ feat) {
    int row = blockIdx.x * (blockDim.x >> 5) + (threadIdx.x >> 5);
    if (row >= NNODES) return;
    int lane = threadIdx.x & 31;
    int beg = g_rowptr[row];
    int end = g_rowptr[row + 1];

    float4 acc = make_float4(0.f, 0.f, 0.f, 0.f);
    for (int base = beg; base < end; base += 32) {
        int cnt = min(32, end - base);
        int   mycol = 0;
        float myval = 0.f;
        if (lane < cnt) {
            int2 e = g_csr[base + lane];
            mycol = e.x;
            myval = __int_as_float(e.y);
        }
        #pragma unroll 8
        for (int j = 0; j < cnt; j++) {
            int   c = __shfl_sync(0xffffffffu, mycol, j);
            float v = __shfl_sync(0xffffffffu, myval, j);
            uint2 h = *reinterpret_cast<const uint2*>(
                          g_featH + (size_t)c * FDIM + lane * 4);
            float2 f0 = __half22float2(*reinterpret_cast<__half2*>(&h.x));
            float2 f1 = __half22float2(*reinterpret_cast<__half2*>(&h.y));
            acc.x = fmaf(v, f0.x, acc.x);
            acc.y = fmaf(v, f0.y, acc.y);
            acc.z = fmaf(v, f1.x, acc.z);
            acc.w = fmaf(v, f1.y, acc.w);
        }
    }
    float4 ft = reinterpret_cast<const float4*>(feat + (size_t)row * FDIM)[lane];
    float4 lp = make_float4(acc.x + ft.x, acc.y + ft.y, acc.z + ft.z, acc.w + ft.w);
    reinterpret_cast<float4*>(g_LfP + (size_t)row * FDIM)[lane] = lp;

    __half2 p0 = __floats2half2_rn(acc.x * ft.x, acc.y * ft.y);
    __half2 p1 = __floats2half2_rn(acc.z * ft.z, acc.w * ft.w);
    uint2 st = make_uint2(*reinterpret_cast<uint32_t*>(&p0),
                          *reinterpret_cast<uint32_t*>(&p1));
    *reinterpret_cast<uint2*>(g_PH + (size_t)row * FDIM + lane * 4) = st;
}

__global__ __launch_bounds__(256)
void spmm2_csr_kernel() {
    int row = blockIdx.x * (blockDim.x >> 5) + (threadIdx.x >> 5);
    if (row >= NNODES) return;
    int lane = threadIdx.x & 31;
    int beg = g_rowptr[row];
    int end = g_rowptr[row + 1];

    float4 acc = make_float4(0.f, 0.f, 0.f, 0.f);
    for (int base = beg; base < end; base += 32) {
        int cnt = min(32, end - base);
        int   mycol = 0;
        float myval = 0.f;
        if (lane < cnt) {
            int2 e = g_csr[base + lane];
            mycol = e.x;
            myval = __int_as_float(e.y);
        }
        #pragma unroll 8
        for (int j = 0; j < cnt; j++) {
            int   c = __shfl_sync(0xffffffffu, mycol, j);
            float v = __shfl_sync(0xffffffffu, myval, j);
            uint2 h = *reinterpret_cast<const uint2*>(
                          g_PH + (size_t)c * FDIM + lane * 4);
            float2 f0 = __half22float2(*reinterpret_cast<__half2*>(&h.x));
            float2 f1 = __half22float2(*reinterpret_cast<__half2*>(&h.y));
            acc.x = fmaf(v, f0.x, acc.x);
            acc.y = fmaf(v, f0.y, acc.y);
            acc.z = fmaf(v, f1.x, acc.z);
            acc.w = fmaf(v, f1.y, acc.w);
        }
    }
    reinterpret_cast<float4*>(g_Li + (size_t)row * FDIM)[lane] = acc;
}

// ---------------------------------------------------------------------------
// Persistent tensor-core GEMM (mma.sync m16n8k8 tf32)  — Round-6 version.
//   out = [LfP ; Li] (N x 256) @ [W1 ; W2] (256 x 128) + (b1+b2)
// grid = 148 CTAs; W converted/staged ONCE per CTA, then loop over row tiles.
// ---------------------------------------------------------------------------
#define WT_STRIDE 260
#define AS_STRIDE 132
#define OFF_WT 0
#define OFF_AS (128 * WT_STRIDE * 4)                  // 133120
#define OFF_BI (OFF_AS + 128 * AS_STRIDE * 4)         // 200704
#define SMEM_GEMM (OFF_BI + 512)                      // 201216

static __device__ __forceinline__ uint32_t f2tf32(float f) {
    uint32_t u;
    asm("cvt.rna.tf32.f32 %0, %1;" : "=r"(u) : "f"(f));
    return u;
}

static __device__ __forceinline__ void mma8(float* d, const uint32_t* a,
                                            uint32_t b0, uint32_t b1) {
    asm volatile(
        "mma.sync.aligned.m16n8k8.row.col.f32.tf32.tf32.f32 "
        "{%0,%1,%2,%3}, {%4,%5,%6,%7}, {%8,%9}, {%0,%1,%2,%3};"
        : "+f"(d[0]), "+f"(d[1]), "+f"(d[2]), "+f"(d[3])
        : "r"(a[0]), "r"(a[1]), "r"(a[2]), "r"(a[3]), "r"(b0), "r"(b1));
}

__global__ __launch_bounds__(256, 1)
void gemm_mma_kernel(const float* __restrict__ W1,
                     const float* __restrict__ b1,
                     const float* __restrict__ W2,
                     const float* __restrict__ b2,
                     float* __restrict__ out) {
    extern __shared__ char smem[];
    uint32_t* Wt   = reinterpret_cast<uint32_t*>(smem + OFF_WT);  // [128][260]
    uint32_t* As   = reinterpret_cast<uint32_t*>(smem + OFF_AS);  // [128][132]
    float*    bias = reinterpret_cast<float*>(smem + OFF_BI);

    const int tid  = threadIdx.x;
    const int w    = tid >> 5;
    const int lane = tid & 31;
    const int tg   = lane & 3;    // k within frag
    const int gid  = lane >> 2;   // row/col within frag
    const int wm   = w & 3;       // row-group
    const int colg = w >> 2;      // col-group

    // ---- stage Wt[n][k] = tf32(W[k][n]) ONCE ----
    #pragma unroll
    for (int it = 0; it < 32; it++) {
        int wt = it * 8 + w;                 // 0..255 warp-tasks
        int k0 = (wt >> 2) * 4;              // 0..252 step 4
        int n  = (wt & 3) * 32 + lane;       // 0..127
        const float* Wsrc = (k0 < 128) ? (W1 + (size_t)k0 * 128)
                                       : (W2 + (size_t)(k0 - 128) * 128);
        uint4 st;
        st.x = f2tf32(Wsrc[0 * 128 + n]);
        st.y = f2tf32(Wsrc[1 * 128 + n]);
        st.z = f2tf32(Wsrc[2 * 128 + n]);
        st.w = f2tf32(Wsrc[3 * 128 + n]);
        *reinterpret_cast<uint4*>(Wt + n * WT_STRIDE + k0) = st;
    }
    if (tid < 128) bias[tid] = b1[tid] + b2[tid];

    for (int tile = blockIdx.x; tile < NTILES; tile += gridDim.x) {
        const int row0 = tile * 128;

        float acc[2][8][4];
        #pragma unroll
        for (int s = 0; s < 2; s++)
            #pragma unroll
            for (int nt = 0; nt < 8; nt++)
                #pragma unroll
                for (int q = 0; q < 4; q++) acc[s][nt][q] = 0.f;

        #pragma unroll
        for (int phase = 0; phase < 2; phase++) {
            const float* src = phase ? g_Li : g_LfP;
            __syncthreads();   // Wt ready / As free

            #pragma unroll
            for (int it = 0; it < 16; it++) {
                int idx = it * 256 + tid;
                int r = idx >> 5;
                int j = idx & 31;
                int row = row0 + r;
                if (row >= NNODES) row = NNODES - 1;
                float4 v = reinterpret_cast<const float4*>(src + (size_t)row * FDIM)[j];
                uint4 st = make_uint4(f2tf32(v.x), f2tf32(v.y), f2tf32(v.z), f2tf32(v.w));
                *reinterpret_cast<uint4*>(As + r * AS_STRIDE + j * 4) = st;
            }
            __syncthreads();

            const int kg0 = phase * 128;
            #pragma unroll 2
            for (int kb = 0; kb < 128; kb += 8) {
                uint32_t a[2][4];
                #pragma unroll
                for (int sub = 0; sub < 2; sub++) {
                    int rb = wm * 32 + sub * 16 + gid;
                    a[sub][0] = As[rb * AS_STRIDE + kb + tg];
                    a[sub][1] = As[(rb + 8) * AS_STRIDE + kb + tg];
                    a[sub][2] = As[rb * AS_STRIDE + kb + 4 + tg];
                    a[sub][3] = As[(rb + 8) * AS_STRIDE + kb + 4 + tg];
                }
                #pragma unroll
                for (int nt = 0; nt < 8; nt++) {
                    int n = colg * 64 + nt * 8 + gid;
                    uint32_t b0 = Wt[n * WT_STRIDE + kg0 + kb + tg];
                    uint32_t b1 = Wt[n * WT_STRIDE + kg0 + kb + 4 + tg];
                    mma8(acc[0][nt], a[0], b0, b1);
                    mma8(acc[1][nt], a[1], b0, b1);
                }
            }
        }

        // ---- epilogue: add bias, float2 stores ----
        #pragma unroll
        for (int sub = 0; sub < 2; sub++) {
            int r0 = row0 + wm * 32 + sub * 16 + gid;
            #pragma unroll
            for (int nt = 0; nt < 8; nt++) {
                int c = colg * 64 + nt * 8 + tg * 2;
                float bx = bias[c], by = bias[c + 1];
                if (r0 < NNODES) {
                    float2 o = make_float2(acc[sub][nt][0] + bx, acc[sub][nt][1] + by);
                    *reinterpret_cast<float2*>(out + (size_t)r0 * FDIM + c) = o;
                }
                if (r0 + 8 < NNODES) {
                    float2 o = make_float2(acc[sub][nt][2] + bx, acc[sub][nt][3] + by);
                    *reinterpret_cast<float2*>(out + (size_t)(r0 + 8) * FDIM + c) = o;
                }
            }
        }
    }
}

// ---------------------------------------------------------------------------
extern "C" void kernel_launch(void* const* d_in, const int* in_sizes, int n_in,
                              void* d_out, int out_size) {
    const float* feat = (const float*)d_in[0];
    const float* eval = (const float*)d_in[1];
    const float* W1   = (const float*)d_in[2];
    const float* b1   = (const float*)d_in[3];
    const float* W2   = (const float*)d_in[4];
    const float* b2   = (const float*)d_in[5];
    const int*   erow = (const int*)d_in[6];
    const int*   ecol = (const int*)d_in[7];
    float*       out  = (float*)d_out;

    const int nnz = in_sizes[1];

    // fp16 feature copy (independent of CSR; issued first)
    {
        const size_t total = (size_t)NNODES * FDIM / 8;
        cvt_feat_kernel<<<(int)((total + 255) / 256), 256>>>(feat);
    }

    // CSR build
    zero_counts_kernel<<<(NNODES + 255) / 256, 256>>>();
    hist_kernel<<<(nnz / 4 + 255) / 256, 256>>>(erow, nnz);
    scan_partial_kernel<<<SCAN_G, SCAN_B>>>();
    scan_bsum_kernel<<<1, 128>>>();
    scan_final_kernel<<<SCAN_G, SCAN_B>>>();
    scatter_kernel<<<(nnz / 4 + 255) / 256, 256>>>(eval, erow, ecol, nnz);

    // SpMM passes (warp per row, fp16 gathers)
    {
        int blocks = (NNODES + 7) / 8;
        spmm1_csr_kernel<<<blocks, 256>>>(feat);
        spmm2_csr_kernel<<<blocks, 256>>>();
    }

    // GEMM (persistent, mma.sync tf32)
    {
        cudaFuncSetAttribute(gemm_mma_kernel,
                             cudaFuncAttributeMaxDynamicSharedMemorySize,
                             SMEM_GEMM);
        gemm_mma_kernel<<<148, 256, SMEM_GEMM>>>(W1, b1, W2, b2, out);
    }
}

// round 10
// speedup vs baseline: 1.4997x; 1.2614x over previous
#include <cuda_runtime.h>
#include <cuda_fp16.h>
#include <cstdint>

#define NNODES 100000
#define FDIM   128
#define NTILES ((NNODES + 127) / 128)

// ---- device-global scratch (allocations forbidden) ----
__device__ __half g_LfPH[(size_t)NNODES * FDIM]; // Lf + feat  fp16 (GEMM A, k 0..127)
__device__ __half g_LiH [(size_t)NNODES * FDIM]; // A @ P      fp16 (GEMM A, k 128..255)
__device__ __half g_featH[(size_t)NNODES * FDIM];// fp16 copy of features
__device__ __half g_PH  [(size_t)NNODES * FDIM]; // Lf * feat fp16 (spmm2 input)
__device__ int    g_rowcnt[NNODES];
__device__ int    g_rowptr[NNODES + 1];
__device__ int    g_rowcur[NNODES];
__device__ int2   g_csr[1600000 + 1024];         // (col, float_bits(val)) packed

#define SCAN_B 1024
#define SCAN_G ((NNODES + SCAN_B - 1) / SCAN_B)  // 98
__device__ int g_bsum[SCAN_G];

// ---------------------------------------------------------------------------
// feat -> fp16 copy (streaming)
// ---------------------------------------------------------------------------
__global__ void cvt_feat_kernel(const float* __restrict__ feat) {
    size_t i = (size_t)blockIdx.x * blockDim.x + threadIdx.x;   // per 8 floats
    const size_t total = (size_t)NNODES * FDIM / 8;
    if (i < total) {
        const float4* s = reinterpret_cast<const float4*>(feat) + i * 2;
        float4 a = s[0], b = s[1];
        __half2 h0 = __floats2half2_rn(a.x, a.y);
        __half2 h1 = __floats2half2_rn(a.z, a.w);
        __half2 h2 = __floats2half2_rn(b.x, b.y);
        __half2 h3 = __floats2half2_rn(b.z, b.w);
        uint4 st = make_uint4(*reinterpret_cast<uint32_t*>(&h0),
                              *reinterpret_cast<uint32_t*>(&h1),
                              *reinterpret_cast<uint32_t*>(&h2),
                              *reinterpret_cast<uint32_t*>(&h3));
        reinterpret_cast<uint4*>(g_featH)[i] = st;
    }
}

// ---------------------------------------------------------------------------
// CSR build: zero counts -> histogram -> 3-stage scan -> scatter
// ---------------------------------------------------------------------------
__global__ void zero_counts_kernel() {
    int i = blockIdx.x * blockDim.x + threadIdx.x;
    if (i < NNODES) g_rowcnt[i] = 0;
}

__global__ void hist_kernel(const int* __restrict__ erow, int nnz) {
    int i = (blockIdx.x * blockDim.x + threadIdx.x) * 4;
    if (i + 3 < nnz) {
        int4 r = *reinterpret_cast<const int4*>(erow + i);
        atomicAdd(&g_rowcnt[r.x], 1);
        atomicAdd(&g_rowcnt[r.y], 1);
        atomicAdd(&g_rowcnt[r.z], 1);
        atomicAdd(&g_rowcnt[r.w], 1);
    } else {
        for (int j = i; j < nnz; j++) atomicAdd(&g_rowcnt[erow[j]], 1);
    }
}

__global__ __launch_bounds__(SCAN_B)
void scan_partial_kernel() {
    __shared__ int s[SCAN_B];
    int tid = threadIdx.x;
    int i = blockIdx.x * SCAN_B + tid;
    s[tid] = (i < NNODES) ? g_rowcnt[i] : 0;
    __syncthreads();
    for (int off = SCAN_B >> 1; off > 0; off >>= 1) {
        if (tid < off) s[tid] += s[tid + off];
        __syncthreads();
    }
    if (tid == 0) g_bsum[blockIdx.x] = s[0];
}

__global__ __launch_bounds__(128, 1)
void scan_bsum_kernel() {
    __shared__ int s[128];
    int tid = threadIdx.x;
    int v = (tid < SCAN_G) ? g_bsum[tid] : 0;
    s[tid] = v;
    __syncthreads();
    for (int off = 1; off < 128; off <<= 1) {
        int t = (tid >= off) ? s[tid - off] : 0;
        __syncthreads();
        s[tid] += t;
        __syncthreads();
    }
    if (tid < SCAN_G) g_bsum[tid] = s[tid] - v;   // exclusive
}

__global__ __launch_bounds__(SCAN_B)
void scan_final_kernel() {
    __shared__ int s[SCAN_B];
    int tid = threadIdx.x;
    int i = blockIdx.x * SCAN_B + tid;
    int v = (i < NNODES) ? g_rowcnt[i] : 0;
    s[tid] = v;
    __syncthreads();
    for (int off = 1; off < SCAN_B; off <<= 1) {
        int t = (tid >= off) ? s[tid - off] : 0;
        __syncthreads();
        s[tid] += t;
        __syncthreads();
    }
    int excl = s[tid] - v + g_bsum[blockIdx.x];
    if (i < NNODES) {
        g_rowptr[i] = excl;
        g_rowcur[i] = excl;
        if (i == NNODES - 1) g_rowptr[NNODES] = excl + v;
    }
}

__global__ void scatter_kernel(const float* __restrict__ eval,
                               const int*   __restrict__ erow,
                               const int*   __restrict__ ecol,
                               int nnz) {
    int i = (blockIdx.x * blockDim.x + threadIdx.x) * 4;
    if (i + 3 < nnz) {
        int4   r = *reinterpret_cast<const int4*>(erow + i);
        int4   c = *reinterpret_cast<const int4*>(ecol + i);
        float4 v = *reinterpret_cast<const float4*>(eval + i);
        int p0 = atomicAdd(&g_rowcur[r.x], 1);
        int p1 = atomicAdd(&g_rowcur[r.y], 1);
        int p2 = atomicAdd(&g_rowcur[r.z], 1);
        int p3 = atomicAdd(&g_rowcur[r.w], 1);
        g_csr[p0] = make_int2(c.x, __float_as_int(v.x));
        g_csr[p1] = make_int2(c.y, __float_as_int(v.y));
        g_csr[p2] = make_int2(c.z, __float_as_int(v.z));
        g_csr[p3] = make_int2(c.w, __float_as_int(v.w));
    } else {
        for (int j = i; j < nnz; j++) {
            int pos = atomicAdd(&g_rowcur[erow[j]], 1);
            g_csr[pos] = make_int2(ecol[j], __float_as_int(eval[j]));
        }
    }
}

// ---------------------------------------------------------------------------
// SpMM-CSR, warp per row, fp16 gathers, fp32 accumulate, fp16 outputs.
// Lane owns cols lane*4..lane*4+3 (8 bytes fp16 per gather row).
// ---------------------------------------------------------------------------
__global__ __launch_bounds__(256)
void spmm1_csr_kernel() {
    int row = blockIdx.x * (blockDim.x >> 5) + (threadIdx.x >> 5);
    if (row >= NNODES) return;
    int lane = threadIdx.x & 31;
    int beg = g_rowptr[row];
    int end = g_rowptr[row + 1];

    float4 acc = make_float4(0.f, 0.f, 0.f, 0.f);
    for (int base = beg; base < end; base += 32) {
        int cnt = min(32, end - base);
        int   mycol = 0;
        float myval = 0.f;
        if (lane < cnt) {
            int2 e = g_csr[base + lane];
            mycol = e.x;
            myval = __int_as_float(e.y);
        }
        #pragma unroll 8
        for (int j = 0; j < cnt; j++) {
            int   c = __shfl_sync(0xffffffffu, mycol, j);
            float v = __shfl_sync(0xffffffffu, myval, j);
            uint2 h = *reinterpret_cast<const uint2*>(
                          g_featH + (size_t)c * FDIM + lane * 4);
            float2 f0 = __half22float2(*reinterpret_cast<__half2*>(&h.x));
            float2 f1 = __half22float2(*reinterpret_cast<__half2*>(&h.y));
            acc.x = fmaf(v, f0.x, acc.x);
            acc.y = fmaf(v, f0.y, acc.y);
            acc.z = fmaf(v, f1.x, acc.z);
            acc.w = fmaf(v, f1.y, acc.w);
        }
    }
    // own features (fp16 copy; same mantissa as downstream storage)
    uint2 hf = *reinterpret_cast<const uint2*>(
                   g_featH + (size_t)row * FDIM + lane * 4);
    float2 t0 = __half22float2(*reinterpret_cast<__half2*>(&hf.x));
    float2 t1 = __half22float2(*reinterpret_cast<__half2*>(&hf.y));

    __half2 l0 = __floats2half2_rn(acc.x + t0.x, acc.y + t0.y);
    __half2 l1 = __floats2half2_rn(acc.z + t1.x, acc.w + t1.y);
    uint2 stl = make_uint2(*reinterpret_cast<uint32_t*>(&l0),
                           *reinterpret_cast<uint32_t*>(&l1));
    *reinterpret_cast<uint2*>(g_LfPH + (size_t)row * FDIM + lane * 4) = stl;

    __half2 p0 = __floats2half2_rn(acc.x * t0.x, acc.y * t0.y);
    __half2 p1 = __floats2half2_rn(acc.z * t1.x, acc.w * t1.y);
    uint2 stp = make_uint2(*reinterpret_cast<uint32_t*>(&p0),
                           *reinterpret_cast<uint32_t*>(&p1));
    *reinterpret_cast<uint2*>(g_PH + (size_t)row * FDIM + lane * 4) = stp;
}

__global__ __launch_bounds__(256)
void spmm2_csr_kernel() {
    int row = blockIdx.x * (blockDim.x >> 5) + (threadIdx.x >> 5);
    if (row >= NNODES) return;
    int lane = threadIdx.x & 31;
    int beg = g_rowptr[row];
    int end = g_rowptr[row + 1];

    float4 acc = make_float4(0.f, 0.f, 0.f, 0.f);
    for (int base = beg; base < end; base += 32) {
        int cnt = min(32, end - base);
        int   mycol = 0;
        float myval = 0.f;
        if (lane < cnt) {
            int2 e = g_csr[base + lane];
            mycol = e.x;
            myval = __int_as_float(e.y);
        }
        #pragma unroll 8
        for (int j = 0; j < cnt; j++) {
            int   c = __shfl_sync(0xffffffffu, mycol, j);
            float v = __shfl_sync(0xffffffffu, myval, j);
            uint2 h = *reinterpret_cast<const uint2*>(
                          g_PH + (size_t)c * FDIM + lane * 4);
            float2 f0 = __half22float2(*reinterpret_cast<__half2*>(&h.x));
            float2 f1 = __half22float2(*reinterpret_cast<__half2*>(&h.y));
            acc.x = fmaf(v, f0.x, acc.x);
            acc.y = fmaf(v, f0.y, acc.y);
            acc.z = fmaf(v, f1.x, acc.z);
            acc.w = fmaf(v, f1.y, acc.w);
        }
    }
    __half2 l0 = __floats2half2_rn(acc.x, acc.y);
    __half2 l1 = __floats2half2_rn(acc.z, acc.w);
    uint2 st = make_uint2(*reinterpret_cast<uint32_t*>(&l0),
                          *reinterpret_cast<uint32_t*>(&l1));
    *reinterpret_cast<uint2*>(g_LiH + (size_t)row * FDIM + lane * 4) = st;
}

// ---------------------------------------------------------------------------
// Persistent tensor-core GEMM (mma.sync m16n8k16 fp16, fp32 accum):
//   out = [LfPH ; LiH] (N x 256) @ [W1 ; W2] (256 x 128) + (b1+b2)
// 256 thr = 8 warps, warp tile 32x64, CTA tile 128x128, K in 2 phases of 128.
// smem (halves): Wt[128][264] (K=256 resident), As[128][136] -> 2 CTAs/SM.
// Bank math: stride 272B/row -> bank (4*gid + tg) mod 32, conflict-free.
// ---------------------------------------------------------------------------
#define WTH 264
#define ASH 136
#define OFF_WT 0
#define OFF_AS (128 * WTH * 2)                       // 67584
#define OFF_BI (OFF_AS + 128 * ASH * 2)              // 102400
#define SMEM_GEMM (OFF_BI + 512)                     // 102912

static __device__ __forceinline__ void mma16(float* d,
                                             uint32_t a0, uint32_t a1,
                                             uint32_t a2, uint32_t a3,
                                             uint32_t b0, uint32_t b1) {
    asm volatile(
        "mma.sync.aligned.m16n8k16.row.col.f32.f16.f16.f32 "
        "{%0,%1,%2,%3}, {%4,%5,%6,%7}, {%8,%9}, {%0,%1,%2,%3};"
        : "+f"(d[0]), "+f"(d[1]), "+f"(d[2]), "+f"(d[3])
        : "r"(a0), "r"(a1), "r"(a2), "r"(a3), "r"(b0), "r"(b1));
}

__global__ __launch_bounds__(256)
void gemm_mma_kernel(const float* __restrict__ W1,
                     const float* __restrict__ b1,
                     const float* __restrict__ W2,
                     const float* __restrict__ b2,
                     float* __restrict__ out) {
    extern __shared__ char smem[];
    __half* Wt   = reinterpret_cast<__half*>(smem + OFF_WT);  // [128][264]
    __half* As   = reinterpret_cast<__half*>(smem + OFF_AS);  // [128][136]
    float*  bias = reinterpret_cast<float*>(smem + OFF_BI);

    const int tid  = threadIdx.x;
    const int w    = tid >> 5;
    const int lane = tid & 31;
    const int tg   = lane & 3;    // k sub-index
    const int gid  = lane >> 2;   // row/col within frag
    const int wm   = w & 3;       // row-group
    const int colg = w >> 2;      // col-group

    // ---- stage Wt[n][k] = fp16(W[k][n]) ONCE (k = 0..255) ----
    #pragma unroll
    for (int it = 0; it < 32; it++) {
        int wt = it * 8 + w;                 // 0..255 warp-tasks
        int k0 = (wt >> 2) * 4;              // 0..252 step 4
        int n  = (wt & 3) * 32 + lane;       // 0..127
        const float* Wsrc = (k0 < 128) ? (W1 + (size_t)k0 * 128)
                                       : (W2 + (size_t)(k0 - 128) * 128);
        __half2 h01 = __floats2half2_rn(Wsrc[0 * 128 + n], Wsrc[1 * 128 + n]);
        __half2 h23 = __floats2half2_rn(Wsrc[2 * 128 + n], Wsrc[3 * 128 + n]);
        uint2 st = make_uint2(*reinterpret_cast<uint32_t*>(&h01),
                              *reinterpret_cast<uint32_t*>(&h23));
        *reinterpret_cast<uint2*>(Wt + n * WTH + k0) = st;
    }
    if (tid < 128) bias[tid] = b1[tid] + b2[tid];

    for (int tile = blockIdx.x; tile < NTILES; tile += gridDim.x) {
        const int row0 = tile * 128;

        float acc[2][8][4];
        #pragma unroll
        for (int s = 0; s < 2; s++)
            #pragma unroll
            for (int nt = 0; nt < 8; nt++)
                #pragma unroll
                for (int q = 0; q < 4; q++) acc[s][nt][q] = 0.f;

        #pragma unroll
        for (int phase = 0; phase < 2; phase++) {
            const __half* src = phase ? g_LiH : g_LfPH;
            __syncthreads();   // Wt ready / As free

            // ---- stage As rows: 128 rows x 16 uint4 (128 halves) ----
            #pragma unroll
            for (int it = 0; it < 8; it++) {
                int idx = it * 256 + tid;    // 0..2047
                int r = idx >> 4;            // 0..127
                int j = idx & 15;            // uint4 within row (16 per row)
                int row = row0 + r;
                if (row >= NNODES) row = NNODES - 1;
                uint4 v = reinterpret_cast<const uint4*>(
                              src + (size_t)row * FDIM)[j];
                *reinterpret_cast<uint4*>(As + r * ASH + j * 8) = v;
            }
            __syncthreads();

            const int kg0 = phase * 128;
            #pragma unroll 2
            for (int kb = 0; kb < 128; kb += 16) {
                uint32_t a[2][4];
                #pragma unroll
                for (int sub = 0; sub < 2; sub++) {
                    int rb = wm * 32 + sub * 16 + gid;
                    const __half* ap0 = As + rb * ASH + kb + 2 * tg;
                    const __half* ap1 = As + (rb + 8) * ASH + kb + 2 * tg;
                    a[sub][0] = *reinterpret_cast<const uint32_t*>(ap0);
                    a[sub][1] = *reinterpret_cast<const uint32_t*>(ap1);
                    a[sub][2] = *reinterpret_cast<const uint32_t*>(ap0 + 8);
                    a[sub][3] = *reinterpret_cast<const uint32_t*>(ap1 + 8);
                }
                #pragma unroll
                for (int nt = 0; nt < 8; nt++) {
                    int n = colg * 64 + nt * 8 + gid;
                    const __half* bp = Wt + n * WTH + kg0 + kb + 2 * tg;
                    uint32_t b0 = *reinterpret_cast<const uint32_t*>(bp);
                    uint32_t b1 = *reinterpret_cast<const uint32_t*>(bp + 8);
                    mma16(acc[0][nt], a[0][0], a[0][1], a[0][2], a[0][3], b0, b1);
                    mma16(acc[1][nt], a[1][0], a[1][1], a[1][2], a[1][3], b0, b1);
                }
            }
        }

        // ---- epilogue: add bias, float2 stores ----
        #pragma unroll
        for (int sub = 0; sub < 2; sub++) {
            int r0 = row0 + wm * 32 + sub * 16 + gid;
            #pragma unroll
            for (int nt = 0; nt < 8; nt++) {
                int c = colg * 64 + nt * 8 + tg * 2;
                float bx = bias[c], by = bias[c + 1];
                if (r0 < NNODES) {
                    float2 o = make_float2(acc[sub][nt][0] + bx, acc[sub][nt][1] + by);
                    *reinterpret_cast<float2*>(out + (size_t)r0 * FDIM + c) = o;
                }
                if (r0 + 8 < NNODES) {
                    float2 o = make_float2(acc[sub][nt][2] + bx, acc[sub][nt][3] + by);
                    *reinterpret_cast<float2*>(out + (size_t)(r0 + 8) * FDIM + c) = o;
                }
            }
        }
    }
}

// ---------------------------------------------------------------------------
extern "C" void kernel_launch(void* const* d_in, const int* in_sizes, int n_in,
                              void* d_out, int out_size) {
    const float* feat = (const float*)d_in[0];
    const float* eval = (const float*)d_in[1];
    const float* W1   = (const float*)d_in[2];
    const float* b1   = (const float*)d_in[3];
    const float* W2   = (const float*)d_in[4];
    const float* b2   = (const float*)d_in[5];
    const int*   erow = (const int*)d_in[6];
    const int*   ecol = (const int*)d_in[7];
    float*       out  = (float*)d_out;

    const int nnz = in_sizes[1];

    // fp16 feature copy (independent of CSR; issued first)
    {
        const size_t total = (size_t)NNODES * FDIM / 8;
        cvt_feat_kernel<<<(int)((total + 255) / 256), 256>>>(feat);
    }

    // CSR build
    zero_counts_kernel<<<(NNODES + 255) / 256, 256>>>();
    hist_kernel<<<(nnz / 4 + 255) / 256, 256>>>(erow, nnz);
    scan_partial_kernel<<<SCAN_G, SCAN_B>>>();
    scan_bsum_kernel<<<1, 128>>>();
    scan_final_kernel<<<SCAN_G, SCAN_B>>>();
    scatter_kernel<<<(nnz / 4 + 255) / 256, 256>>>(eval, erow, ecol, nnz);

    // SpMM passes (warp per row, fp16 gathers + fp16 outputs)
    {
        int blocks = (NNODES + 7) / 8;
        spmm1_csr_kernel<<<blocks, 256>>>();
        spmm2_csr_kernel<<<blocks, 256>>>();
    }

    // GEMM (persistent, mma.sync fp16 m16n8k16, 2 CTAs/SM)
    {
        cudaFuncSetAttribute(gemm_mma_kernel,
                             cudaFuncAttributeMaxDynamicSharedMemorySize,
                             SMEM_GEMM);
        gemm_mma_kernel<<<296, 256, SMEM_GEMM>>>(W1, b1, W2, b2, out);
    }
}